// round 1
// baseline (speedup 1.0000x reference)
#include <cuda_runtime.h>
#include <math.h>

// Problem dims (fixed by the reference)
#define MDIM 8192   // B*S tokens
#define HDIM 1024
#define RDIM 2048
#define LDIM 2048
#define SDIM 2048
#define BDIM 4

// ---------------- scratch (device globals; no allocation APIs) --------------
__device__ float g_f   [(size_t)MDIM * RDIM];
__device__ float g_g   [(size_t)MDIM * RDIM];   // sigmoid(input) -> becomes gc
__device__ float g_c   [(size_t)MDIM * RDIM];   // silu(value)
__device__ float g_q   [(size_t)MDIM * RDIM];
__device__ float g_up  [(size_t)MDIM * LDIM];   // up -> becomes up*silu(gate)
__device__ float g_gate[(size_t)MDIM * LDIM];   // silu(gate)
__device__ float g_ro  [(size_t)MDIM * RDIM];   // readout

// ---------------- GEMM: C[M,N] = act( A[M,K] * B[N,K]^T ) ------------------
#define BM 128
#define BN 128
#define BK 16

#define ACT_NONE 0
#define ACT_TANH 1
#define ACT_SIGMOID 2
#define ACT_SILU 3

__device__ __forceinline__ float act_apply(float x, int act) {
    if (act == ACT_TANH)    return tanhf(x);
    if (act == ACT_SIGMOID) return 1.0f / (1.0f + __expf(-x));
    if (act == ACT_SILU)    return x / (1.0f + __expf(-x));
    return x;
}

// One K-pass of the tiled GEMM, accumulating into acc. Safe to call twice
// (leading __syncthreads protects shared memory from the previous pass).
__device__ __forceinline__ void gemm_pass(
    const float* __restrict__ A, const float* __restrict__ Bw, int K,
    int bm, int bn, int tid, float (&acc)[8][8],
    float (*As)[BM], float (*Bs)[BN])
{
    const int tr = tid >> 4;      // 0..15
    const int tc = tid & 15;      // 0..15
    const float* Abase = A  + (size_t)bm * BM * K;
    const float* Bbase = Bw + (size_t)bn * BN * K;

    float4 ra[2], rb[2];

    auto ldg = [&](int k0) {
#pragma unroll
        for (int i = 0; i < 2; i++) {
            int v   = tid + i * 256;      // float4 index 0..511
            int row = v >> 2;             // 0..127
            int c4  = (v & 3) << 2;       // 0,4,8,12
            ra[i] = *(const float4*)(Abase + (size_t)row * K + k0 + c4);
            rb[i] = *(const float4*)(Bbase + (size_t)row * K + k0 + c4);
        }
    };
    auto sts = [&]() {
#pragma unroll
        for (int i = 0; i < 2; i++) {
            int v   = tid + i * 256;
            int row = v >> 2;
            int c4  = (v & 3) << 2;
            As[c4 + 0][row] = ra[i].x;
            As[c4 + 1][row] = ra[i].y;
            As[c4 + 2][row] = ra[i].z;
            As[c4 + 3][row] = ra[i].w;
            Bs[c4 + 0][row] = rb[i].x;
            Bs[c4 + 1][row] = rb[i].y;
            Bs[c4 + 2][row] = rb[i].z;
            Bs[c4 + 3][row] = rb[i].w;
        }
    };
    auto compute = [&]() {
#pragma unroll
        for (int k = 0; k < BK; k++) {
            float a[8], b[8];
            *(float4*)&a[0] = *(const float4*)&As[k][tr * 8];
            *(float4*)&a[4] = *(const float4*)&As[k][tr * 8 + 4];
            *(float4*)&b[0] = *(const float4*)&Bs[k][tc * 8];
            *(float4*)&b[4] = *(const float4*)&Bs[k][tc * 8 + 4];
#pragma unroll
            for (int i = 0; i < 8; i++)
#pragma unroll
                for (int j = 0; j < 8; j++)
                    acc[i][j] += a[i] * b[j];
        }
    };

    ldg(0);
    __syncthreads();   // previous pass (if any) done reading smem
    sts();
    __syncthreads();
    for (int k0 = BK; k0 < K; k0 += BK) {
        ldg(k0);       // prefetch next tile to registers
        compute();     // compute on current smem tile
        __syncthreads();
        sts();
        __syncthreads();
    }
    compute();
}

// A2/B2 == nullptr -> single GEMM. Otherwise acc += A2*B2^T too (fused sum).
__global__ __launch_bounds__(256, 2)
void gemm_tn_kernel(const float* __restrict__ A,  const float* __restrict__ Bw,  int K1,
                    const float* __restrict__ A2, const float* __restrict__ B2, int K2,
                    float* __restrict__ C, int Nld, int act)
{
    __shared__ float As[BK][BM];
    __shared__ float Bs[BK][BN];

    float acc[8][8];
#pragma unroll
    for (int i = 0; i < 8; i++)
#pragma unroll
        for (int j = 0; j < 8; j++) acc[i][j] = 0.0f;

    const int tid = threadIdx.x;
    const int bm = blockIdx.y, bn = blockIdx.x;

    gemm_pass(A, Bw, K1, bm, bn, tid, acc, As, Bs);
    if (A2) gemm_pass(A2, B2, K2, bm, bn, tid, acc, As, Bs);

    const int tr = tid >> 4, tc = tid & 15;
    const size_t crow = (size_t)bm * BM + tr * 8;
    const int    ccol = bn * BN + tc * 8;
#pragma unroll
    for (int i = 0; i < 8; i++) {
        float4 o0, o1;
        o0.x = act_apply(acc[i][0], act);
        o0.y = act_apply(acc[i][1], act);
        o0.z = act_apply(acc[i][2], act);
        o0.w = act_apply(acc[i][3], act);
        o1.x = act_apply(acc[i][4], act);
        o1.y = act_apply(acc[i][5], act);
        o1.z = act_apply(acc[i][6], act);
        o1.w = act_apply(acc[i][7], act);
        *(float4*)(C + (crow + i) * (size_t)Nld + ccol)     = o0;
        *(float4*)(C + (crow + i) * (size_t)Nld + ccol + 4) = o1;
    }
}

// ------------- elementwise combine: g *= c ; up *= silu_gate ---------------
__global__ void combine_kernel(float* __restrict__ g, const float* __restrict__ c,
                               float* __restrict__ up, const float* __restrict__ sg)
{
    size_t i = (size_t)blockIdx.x * blockDim.x + threadIdx.x;   // float4 index
    float4 a = ((const float4*)g)[i];
    float4 b = ((const float4*)c)[i];
    a.x *= b.x; a.y *= b.y; a.z *= b.z; a.w *= b.w;
    ((float4*)g)[i] = a;

    float4 u = ((const float4*)up)[i];
    float4 s = ((const float4*)sg)[i];
    u.x *= s.x; u.y *= s.y; u.z *= s.z; u.w *= s.w;
    ((float4*)up)[i] = u;
}

// ------------- sequential diagonal recurrence over S -----------------------
// One thread per (b, r) lane; loads are state-independent -> deep MLP.
__global__ void scan_kernel(const float* __restrict__ f, const float* __restrict__ gc,
                            const float* __restrict__ q, const float* __restrict__ init,
                            float* __restrict__ ro)
{
    int lane = blockIdx.x * blockDim.x + threadIdx.x;  // 0..8191
    int b = lane >> 11;          // / 2048
    int r = lane & (RDIM - 1);
    size_t base = (size_t)b * SDIM * RDIM + r;
    float state = init[r];
#pragma unroll 4
    for (int s = 0; s < SDIM; s++) {
        size_t idx = base + (size_t)s * RDIM;
        float fv  = __ldg(f + idx);
        float gcv = __ldg(gc + idx);
        float qv  = __ldg(q + idx);
        state = fmaf(fv, state, gcv);
        float z = qv * state;
        ro[idx] = z / (1.0f + __expf(-z));     // silu
    }
}

// ---------------------------- launch ---------------------------------------
extern "C" void kernel_launch(void* const* d_in, const int* in_sizes, int n_in,
                              void* d_out, int out_size)
{
    const float* x    = (const float*)d_in[0];
    const float* Wf   = (const float*)d_in[1];
    const float* Wi   = (const float*)d_in[2];
    const float* Wv   = (const float*)d_in[3];
    const float* Wq   = (const float*)d_in[4];
    const float* Wro  = (const float*)d_in[5];   // [H, R]
    const float* Wup  = (const float*)d_in[6];
    const float* Wg   = (const float*)d_in[7];
    const float* Wd   = (const float*)d_in[8];   // [H, L]
    const float* init = (const float*)d_in[9];
    float* out = (float*)d_out;

    float *pf, *pg, *pc, *pq, *pup, *pgate, *pro;
    cudaGetSymbolAddress((void**)&pf,    g_f);
    cudaGetSymbolAddress((void**)&pg,    g_g);
    cudaGetSymbolAddress((void**)&pc,    g_c);
    cudaGetSymbolAddress((void**)&pq,    g_q);
    cudaGetSymbolAddress((void**)&pup,   g_up);
    cudaGetSymbolAddress((void**)&pgate, g_gate);
    cudaGetSymbolAddress((void**)&pro,   g_ro);

    dim3 blk(256);
    dim3 gproj(RDIM / BN, MDIM / BM);   // (16, 64)
    dim3 gout (HDIM / BN, MDIM / BM);   // (8, 64)

    // 6 projections with fused activations
    gemm_tn_kernel<<<gproj, blk>>>(x, Wf,  HDIM, nullptr, nullptr, 0, pf,    RDIM, ACT_TANH);
    gemm_tn_kernel<<<gproj, blk>>>(x, Wi,  HDIM, nullptr, nullptr, 0, pg,    RDIM, ACT_SIGMOID);
    gemm_tn_kernel<<<gproj, blk>>>(x, Wv,  HDIM, nullptr, nullptr, 0, pc,    RDIM, ACT_SILU);
    gemm_tn_kernel<<<gproj, blk>>>(x, Wq,  HDIM, nullptr, nullptr, 0, pq,    RDIM, ACT_NONE);
    gemm_tn_kernel<<<gproj, blk>>>(x, Wup, HDIM, nullptr, nullptr, 0, pup,   LDIM, ACT_NONE);
    gemm_tn_kernel<<<gproj, blk>>>(x, Wg,  HDIM, nullptr, nullptr, 0, pgate, LDIM, ACT_SILU);

    // gc = g*c (into g_g), h = up*silu(gate) (into g_up)
    {
        size_t n4 = ((size_t)MDIM * RDIM) / 4;     // 4,194,304
        combine_kernel<<<(unsigned)(n4 / 256), 256>>>(pg, pc, pup, pgate);
    }

    // diagonal recurrence + readout
    scan_kernel<<<128, 64>>>(pf, pg, pq, init, pro);

    // out = readout @ Wro^T + h @ Wd^T
    gemm_tn_kernel<<<gout, blk>>>(pro, Wro, RDIM, pup, Wd, LDIM, out, HDIM, ACT_NONE);
}

// round 3
// speedup vs baseline: 2.9589x; 2.9589x over previous
#include <cuda_runtime.h>
#include <cuda_bf16.h>
#include <stdint.h>
#include <math.h>

// ---------------- problem dims ----------------
#define MDIM 8192      // B*S
#define HDIM 1024
#define RDIM 2048
#define SDIM 2048
#define NPROJ 12288    // 6 * 2048 stacked projection outputs
#define KOUT 4096      // R + L for the output GEMM
#define NCH 64         // scan chunks
#define CH 32          // tokens per chunk

// ---------------- scratch (device globals) ----------------
__device__ float          g_P   [(size_t)MDIM * NPROJ];
__device__ __nv_bfloat16  g_xhi [(size_t)MDIM * HDIM];
__device__ __nv_bfloat16  g_xlo [(size_t)MDIM * HDIM];
__device__ __nv_bfloat16  g_w6hi[(size_t)NPROJ * HDIM];
__device__ __nv_bfloat16  g_w6lo[(size_t)NPROJ * HDIM];
__device__ __nv_bfloat16  g_wohi[(size_t)HDIM * KOUT];
__device__ __nv_bfloat16  g_wolo[(size_t)HDIM * KOUT];
__device__ __nv_bfloat16  g_a2hi[(size_t)MDIM * KOUT];
__device__ __nv_bfloat16  g_a2lo[(size_t)MDIM * KOUT];
__device__ float          g_Fc  [(size_t)4 * NCH * RDIM];
__device__ float          g_Gc  [(size_t)4 * NCH * RDIM];
__device__ float          g_Sc  [(size_t)4 * NCH * RDIM];

// ---------------- helpers ----------------
__device__ __forceinline__ uint32_t smem_u32(const void* p) {
    uint32_t a;
    asm("{ .reg .u64 t; cvta.to.shared.u64 t, %1; cvt.u32.u64 %0, t; }" : "=r"(a) : "l"(p));
    return a;
}
__device__ __forceinline__ void cp16(uint32_t s, const void* g) {
    asm volatile("cp.async.cg.shared.global [%0], [%1], 16;" :: "r"(s), "l"(g));
}
#define CP_COMMIT() asm volatile("cp.async.commit_group;" ::: "memory")
#define CP_WAIT2()  asm volatile("cp.async.wait_group 2;" ::: "memory")

__device__ __forceinline__ void ldm_x4(uint32_t (&d)[4], uint32_t a) {
    asm volatile("ldmatrix.sync.aligned.m8n8.x4.shared.b16 {%0,%1,%2,%3}, [%4];"
        : "=r"(d[0]), "=r"(d[1]), "=r"(d[2]), "=r"(d[3]) : "r"(a));
}
__device__ __forceinline__ void mma_bf16(float (&c)[4], const uint32_t (&a)[4], const uint32_t* b) {
    asm volatile("mma.sync.aligned.m16n8k16.row.col.f32.bf16.bf16.f32 "
        "{%0,%1,%2,%3}, {%4,%5,%6,%7}, {%8,%9}, {%0,%1,%2,%3};"
        : "+f"(c[0]), "+f"(c[1]), "+f"(c[2]), "+f"(c[3])
        : "r"(a[0]), "r"(a[1]), "r"(a[2]), "r"(a[3]), "r"(b[0]), "r"(b[1]));
}

// ---------------- activation ----------------
#define ACT_NONE 0
#define ACT_TANH 1
#define ACT_SIGMOID 2
#define ACT_SILU 3
__device__ __forceinline__ float act_apply(float x, int act) {
    if (act == ACT_TANH)    return tanhf(x);
    if (act == ACT_SIGMOID) return 1.0f / (1.0f + __expf(-x));
    if (act == ACT_SILU)    return x / (1.0f + __expf(-x));
    return x;
}

// ================= HMMA bf16 3-pass split GEMM =================
// C[M,N] = act(A*B^T), A ~ Ahi+Alo, B ~ Bhi+Blo; keep AhiBhi + AloBhi + AhiBlo.
// CTA 128x128, KC=64, 3-stage cp.async pipeline, 8 warps (2x4), warp 64x32.
#define BM 128
#define BN 128
#define KC 64
#define RSTR 144                       // smem row stride bytes (64 bf16 + 8 pad)
#define TILE_B (128 * RSTR)            // 18432 per operand tile
#define STAGE_B (4 * TILE_B)           // Ahi,Alo,Bhi,Blo = 73728
#define GEMM_SMEM (3 * STAGE_B)        // 221184

__global__ void __launch_bounds__(256)
gemm_hmma(const __nv_bfloat16* __restrict__ Ahi, const __nv_bfloat16* __restrict__ Alo,
          const __nv_bfloat16* __restrict__ Bhi, const __nv_bfloat16* __restrict__ Blo,
          int K, float* __restrict__ C, int ldc, unsigned actlut)
{
    extern __shared__ char smem[];
    const uint32_t sbase = smem_u32(smem);
    const int tid  = threadIdx.x;
    const int bm   = blockIdx.y, bn = blockIdx.x;
    const int wid  = tid >> 5, lane = tid & 31;
    const int wm   = wid >> 2, wn = wid & 3;        // 2 x 4 warp grid

    const __nv_bfloat16* srcs[4] = {
        Ahi + (size_t)bm * BM * K, Alo + (size_t)bm * BM * K,
        Bhi + (size_t)bn * BN * K, Blo + (size_t)bn * BN * K };

    // per-thread load geometry: col16 fixed, rows tid/8 + 32*i
    const int lcol = tid & 7;
    const int lrow0 = tid >> 3;

    auto load_stage = [&](int s) {
        const uint32_t sb = sbase + (uint32_t)(s % 3) * STAGE_B;
        const int k0 = s * KC;
#pragma unroll
        for (int t = 0; t < 4; t++) {
            const __nv_bfloat16* src = srcs[t] + k0 + lcol * 8;
            const uint32_t so = sb + t * TILE_B + lcol * 16;
#pragma unroll
            for (int i = 0; i < 4; i++) {
                int row = lrow0 + 32 * i;
                cp16(so + row * RSTR, src + (size_t)row * K);
            }
        }
    };

    // ldmatrix lane address geometry
    const int quad = lane >> 3, r8 = lane & 7;
    const uint32_t aoff = (uint32_t)((wm * 64 + r8 + (quad & 1) * 8) * RSTR + (quad >> 1) * 16);
    const uint32_t boff = (uint32_t)((wn * 32 + r8 + (quad >> 1) * 8) * RSTR + (quad & 1) * 16);

    float acc[4][4][4];
#pragma unroll
    for (int mi = 0; mi < 4; mi++)
#pragma unroll
        for (int nj = 0; nj < 4; nj++)
#pragma unroll
            for (int e = 0; e < 4; e++) acc[mi][nj][e] = 0.0f;

    const int ns = K / KC;
    load_stage(0); CP_COMMIT();
    load_stage(1); CP_COMMIT();

    for (int s = 0; s < ns; s++) {
        if (s + 2 < ns) load_stage(s + 2);
        CP_COMMIT();
        CP_WAIT2();
        __syncthreads();

        const uint32_t st = sbase + (uint32_t)(s % 3) * STAGE_B;
        const uint32_t aH = st + aoff;
        const uint32_t aL = aH + TILE_B;
        const uint32_t bH = st + 2 * TILE_B + boff;
        const uint32_t bL = bH + TILE_B;

#pragma unroll
        for (int ks = 0; ks < 4; ks++) {
            const uint32_t kb = ks * 32;
            uint32_t afh[4][4], afl[4][4], bf[4][2];

            // A-hi fragments (4 x m16)
#pragma unroll
            for (int mi = 0; mi < 4; mi++) ldm_x4(afh[mi], aH + mi * (16 * RSTR) + kb);
            // B-hi fragments (4 x n8 via two x4)
            {
                uint32_t t0[4], t1[4];
                ldm_x4(t0, bH + kb);
                ldm_x4(t1, bH + 16 * RSTR + kb);
                bf[0][0] = t0[0]; bf[0][1] = t0[1]; bf[1][0] = t0[2]; bf[1][1] = t0[3];
                bf[2][0] = t1[0]; bf[2][1] = t1[1]; bf[3][0] = t1[2]; bf[3][1] = t1[3];
            }
            // pass 1: Ahi * Bhi
#pragma unroll
            for (int mi = 0; mi < 4; mi++)
#pragma unroll
                for (int nj = 0; nj < 4; nj++) mma_bf16(acc[mi][nj], afh[mi], bf[nj]);
            // A-lo fragments
#pragma unroll
            for (int mi = 0; mi < 4; mi++) ldm_x4(afl[mi], aL + mi * (16 * RSTR) + kb);
            // pass 2: Alo * Bhi
#pragma unroll
            for (int mi = 0; mi < 4; mi++)
#pragma unroll
                for (int nj = 0; nj < 4; nj++) mma_bf16(acc[mi][nj], afl[mi], bf[nj]);
            // B-lo fragments (overwrite bf)
            {
                uint32_t t0[4], t1[4];
                ldm_x4(t0, bL + kb);
                ldm_x4(t1, bL + 16 * RSTR + kb);
                bf[0][0] = t0[0]; bf[0][1] = t0[1]; bf[1][0] = t0[2]; bf[1][1] = t0[3];
                bf[2][0] = t1[0]; bf[2][1] = t1[1]; bf[3][0] = t1[2]; bf[3][1] = t1[3];
            }
            // pass 3: Ahi * Blo
#pragma unroll
            for (int mi = 0; mi < 4; mi++)
#pragma unroll
                for (int nj = 0; nj < 4; nj++) mma_bf16(acc[mi][nj], afh[mi], bf[nj]);
        }
        __syncthreads();
    }

    // ---- epilogue ----
    const int act  = (int)((actlut >> ((bn >> 4) * 4)) & 15u);  // BN=128 within one 2048 block
    const int row0 = bm * BM + wm * 64 + (lane >> 2);
    const int col0 = bn * BN + wn * 32 + 2 * (lane & 3);
#pragma unroll
    for (int mi = 0; mi < 4; mi++) {
#pragma unroll
        for (int nj = 0; nj < 4; nj++) {
            float2 v0, v1;
            v0.x = act_apply(acc[mi][nj][0], act);
            v0.y = act_apply(acc[mi][nj][1], act);
            v1.x = act_apply(acc[mi][nj][2], act);
            v1.y = act_apply(acc[mi][nj][3], act);
            size_t base = (size_t)(row0 + mi * 16) * ldc + col0 + nj * 8;
            *(float2*)(C + base)                 = v0;
            *(float2*)(C + base + (size_t)8 * ldc) = v1;
        }
    }
}

// ================= conversion kernels =================
__device__ __forceinline__ void split_bf16(float v, __nv_bfloat16& hi, __nv_bfloat16& lo) {
    hi = __float2bfloat16(v);
    lo = __float2bfloat16(v - __bfloat162float(hi));
}

__global__ void conv_x_kernel(const float* __restrict__ x,
                              __nv_bfloat16* __restrict__ hi, __nv_bfloat16* __restrict__ lo) {
    size_t i = (size_t)blockIdx.x * blockDim.x + threadIdx.x;
    split_bf16(x[i], hi[i], lo[i]);
}

__global__ void conv_w6_kernel(const float* __restrict__ w0, const float* __restrict__ w1,
                               const float* __restrict__ w2, const float* __restrict__ w3,
                               const float* __restrict__ w4, const float* __restrict__ w5,
                               __nv_bfloat16* __restrict__ hi, __nv_bfloat16* __restrict__ lo) {
    size_t i = (size_t)blockIdx.x * blockDim.x + threadIdx.x;     // [0, 12288*1024)
    int n = (int)(i >> 10);
    int k = (int)(i & 1023);
    int w = n >> 11, r = n & 2047;
    const float* src = (w == 0) ? w0 : (w == 1) ? w1 : (w == 2) ? w2
                     : (w == 3) ? w3 : (w == 4) ? w4 : w5;
    split_bf16(src[(size_t)r * 1024 + k], hi[i], lo[i]);
}

__global__ void conv_wout_kernel(const float* __restrict__ Wro, const float* __restrict__ Wd,
                                 __nv_bfloat16* __restrict__ hi, __nv_bfloat16* __restrict__ lo) {
    size_t i = (size_t)blockIdx.x * blockDim.x + threadIdx.x;     // [0, 1024*4096)
    int h = (int)(i >> 12);
    int j = (int)(i & 4095);
    float v = (j < 2048) ? Wro[(size_t)h * 2048 + j] : Wd[(size_t)h * 2048 + (j - 2048)];
    split_bf16(v, hi[i], lo[i]);
}

// ================= scan (two-level, chunked) =================
// P cols: f[0:2048) g[2048:4096) c[4096:6144) q[6144:8192) up[8192:10240) gate_silu[10240:12288)
__global__ void scanA_kernel(const float* __restrict__ P,
                             float* __restrict__ Fc, float* __restrict__ Gc) {
    int r  = blockIdx.x * blockDim.x + threadIdx.x;
    int bc = blockIdx.y;
    int b = bc >> 6, ch = bc & 63;
    const float* row = P + (size_t)(b * SDIM + ch * CH) * NPROJ;
    float F = 1.0f, G = 0.0f;
#pragma unroll 4
    for (int t = 0; t < CH; t++) {
        float f = row[r];
        float g = row[2048 + r];
        float c = row[4096 + r];
        G = fmaf(f, G, g * c);
        F *= f;
        row += NPROJ;
    }
    Fc[(size_t)bc * RDIM + r] = F;
    Gc[(size_t)bc * RDIM + r] = G;
}

__global__ void scanB_kernel(const float* __restrict__ Fc, const float* __restrict__ Gc,
                             const float* __restrict__ init, float* __restrict__ Sc) {
    int i = blockIdx.x * blockDim.x + threadIdx.x;
    int b = i >> 11, r = i & 2047;
    float state = init[r];
    for (int ch = 0; ch < NCH; ch++) {
        size_t idx = (size_t)(b * NCH + ch) * RDIM + r;
        Sc[idx] = state;
        state = fmaf(Fc[idx], state, Gc[idx]);
    }
}

__global__ void scanC_kernel(const float* __restrict__ P, const float* __restrict__ Sc,
                             __nv_bfloat16* __restrict__ a2hi, __nv_bfloat16* __restrict__ a2lo) {
    int r  = blockIdx.x * blockDim.x + threadIdx.x;
    int bc = blockIdx.y;
    int b = bc >> 6, ch = bc & 63;
    int m0 = b * SDIM + ch * CH;
    const float* row = P + (size_t)m0 * NPROJ;
    float state = Sc[(size_t)bc * RDIM + r];
#pragma unroll 4
    for (int t = 0; t < CH; t++) {
        float f = row[r];
        float g = row[2048 + r];
        float c = row[4096 + r];
        float q = row[6144 + r];
        state = fmaf(f, state, g * c);
        float z = q * state;
        float ro = z / (1.0f + __expf(-z));
        __nv_bfloat16 hi, lo;
        split_bf16(ro, hi, lo);
        size_t oi = (size_t)(m0 + t) * KOUT + r;
        a2hi[oi] = hi;
        a2lo[oi] = lo;
        row += NPROJ;
    }
}

__global__ void hcomb_kernel(const float* __restrict__ P,
                             __nv_bfloat16* __restrict__ a2hi, __nv_bfloat16* __restrict__ a2lo) {
    size_t i = (size_t)blockIdx.x * blockDim.x + threadIdx.x;
    int m = (int)(i >> 11);
    int l = (int)(i & 2047);
    const float* row = P + (size_t)m * NPROJ;
    float h = row[8192 + l] * row[10240 + l];
    __nv_bfloat16 hi, lo;
    split_bf16(h, hi, lo);
    size_t oi = (size_t)m * KOUT + 2048 + l;
    a2hi[oi] = hi;
    a2lo[oi] = lo;
}

// ================= launch =================
extern "C" void kernel_launch(void* const* d_in, const int* in_sizes, int n_in,
                              void* d_out, int out_size)
{
    const float* x    = (const float*)d_in[0];
    const float* Wf   = (const float*)d_in[1];
    const float* Wi   = (const float*)d_in[2];
    const float* Wv   = (const float*)d_in[3];
    const float* Wq   = (const float*)d_in[4];
    const float* Wro  = (const float*)d_in[5];
    const float* Wup  = (const float*)d_in[6];
    const float* Wg   = (const float*)d_in[7];
    const float* Wd   = (const float*)d_in[8];
    const float* init = (const float*)d_in[9];
    float* out = (float*)d_out;

    float *pP, *pFc, *pGc, *pSc;
    __nv_bfloat16 *pxhi, *pxlo, *pw6hi, *pw6lo, *pwohi, *pwolo, *pa2hi, *pa2lo;
    cudaGetSymbolAddress((void**)&pP,    g_P);
    cudaGetSymbolAddress((void**)&pxhi,  g_xhi);
    cudaGetSymbolAddress((void**)&pxlo,  g_xlo);
    cudaGetSymbolAddress((void**)&pw6hi, g_w6hi);
    cudaGetSymbolAddress((void**)&pw6lo, g_w6lo);
    cudaGetSymbolAddress((void**)&pwohi, g_wohi);
    cudaGetSymbolAddress((void**)&pwolo, g_wolo);
    cudaGetSymbolAddress((void**)&pa2hi, g_a2hi);
    cudaGetSymbolAddress((void**)&pa2lo, g_a2lo);
    cudaGetSymbolAddress((void**)&pFc,   g_Fc);
    cudaGetSymbolAddress((void**)&pGc,   g_Gc);
    cudaGetSymbolAddress((void**)&pSc,   g_Sc);

    cudaFuncSetAttribute(gemm_hmma, cudaFuncAttributeMaxDynamicSharedMemorySize, GEMM_SMEM);

    // conversions
    conv_x_kernel   <<<(MDIM * HDIM) / 256, 256>>>(x, pxhi, pxlo);
    conv_w6_kernel  <<<(NPROJ * HDIM) / 256, 256>>>(Wf, Wi, Wv, Wq, Wup, Wg, pw6hi, pw6lo);
    conv_wout_kernel<<<(HDIM * KOUT) / 256, 256>>>(Wro, Wd, pwohi, pwolo);

    // GEMM1: P = act( x @ W6^T ); acts per 2048-col block: tanh,sig,silu,none,none,silu
    {
        dim3 grid(NPROJ / BN, MDIM / BM);   // (96, 64)
        gemm_hmma<<<grid, 256, GEMM_SMEM>>>(pxhi, pxlo, pw6hi, pw6lo, HDIM, pP, NPROJ, 0x300321u);
    }

    // scan
    {
        dim3 gA(RDIM / 256, 4 * NCH);
        scanA_kernel<<<gA, 256>>>(pP, pFc, pGc);
        scanB_kernel<<<32, 256>>>(pFc, pGc, init, pSc);
        scanC_kernel<<<gA, 256>>>(pP, pSc, pa2hi, pa2lo);
        hcomb_kernel<<<(MDIM * RDIM) / 256, 256>>>(pP, pa2hi, pa2lo);
    }

    // GEMM2: out = [ro | h] @ [Wro | Wd]^T
    {
        dim3 grid(HDIM / BN, MDIM / BM);    // (8, 64)
        gemm_hmma<<<grid, 256, GEMM_SMEM>>>(pa2hi, pa2lo, pwohi, pwolo, KOUT, out, HDIM, 0u);
    }
}

// round 4
// speedup vs baseline: 3.0244x; 1.0221x over previous
#include <cuda_runtime.h>
#include <cuda_bf16.h>
#include <stdint.h>
#include <math.h>

// ---------------- problem dims ----------------
#define MDIM 8192      // B*S
#define HDIM 1024
#define RDIM 2048
#define SDIM 2048
#define NPROJ 12288    // 6 * 2048 stacked projection outputs
#define KOUT 4096      // R + L for the output GEMM
#define NCH 64         // scan chunks
#define CH 32          // tokens per chunk

// ---------------- scratch (device globals) ----------------
__device__ float          g_P   [(size_t)MDIM * NPROJ];
__device__ __nv_bfloat16  g_xhi [(size_t)MDIM * HDIM];
__device__ __nv_bfloat16  g_xlo [(size_t)MDIM * HDIM];
__device__ __nv_bfloat16  g_w6hi[(size_t)NPROJ * HDIM];
__device__ __nv_bfloat16  g_w6lo[(size_t)NPROJ * HDIM];
__device__ __nv_bfloat16  g_wohi[(size_t)HDIM * KOUT];
__device__ __nv_bfloat16  g_wolo[(size_t)HDIM * KOUT];
__device__ __nv_bfloat16  g_a2hi[(size_t)MDIM * KOUT];
__device__ __nv_bfloat16  g_a2lo[(size_t)MDIM * KOUT];
__device__ float          g_Fc  [(size_t)4 * NCH * RDIM];
__device__ float          g_Gc  [(size_t)4 * NCH * RDIM];
__device__ float          g_Sc  [(size_t)4 * NCH * RDIM];

// ---------------- helpers ----------------
__device__ __forceinline__ uint32_t smem_u32(const void* p) {
    uint32_t a;
    asm("{ .reg .u64 t; cvta.to.shared.u64 t, %1; cvt.u32.u64 %0, t; }" : "=r"(a) : "l"(p));
    return a;
}
__device__ __forceinline__ void cp16(uint32_t s, const void* g) {
    asm volatile("cp.async.cg.shared.global [%0], [%1], 16;" :: "r"(s), "l"(g));
}
#define CP_COMMIT() asm volatile("cp.async.commit_group;" ::: "memory")
template<int N> __device__ __forceinline__ void cp_wait() {
    asm volatile("cp.async.wait_group %0;" :: "n"(N) : "memory");
}

__device__ __forceinline__ void ldm_x4(uint32_t (&d)[4], uint32_t a) {
    asm volatile("ldmatrix.sync.aligned.m8n8.x4.shared.b16 {%0,%1,%2,%3}, [%4];"
        : "=r"(d[0]), "=r"(d[1]), "=r"(d[2]), "=r"(d[3]) : "r"(a));
}
__device__ __forceinline__ void mma_bf16(float (&c)[4], const uint32_t (&a)[4], const uint32_t* b) {
    asm volatile("mma.sync.aligned.m16n8k16.row.col.f32.bf16.bf16.f32 "
        "{%0,%1,%2,%3}, {%4,%5,%6,%7}, {%8,%9}, {%0,%1,%2,%3};"
        : "+f"(c[0]), "+f"(c[1]), "+f"(c[2]), "+f"(c[3])
        : "r"(a[0]), "r"(a[1]), "r"(a[2]), "r"(a[3]), "r"(b[0]), "r"(b[1]));
}

// ---------------- activation ----------------
#define ACT_NONE 0
#define ACT_TANH 1
#define ACT_SIGMOID 2
#define ACT_SILU 3
__device__ __forceinline__ float act_apply(float x, int act) {
    if (act == ACT_TANH)    return tanhf(x);
    if (act == ACT_SIGMOID) return 1.0f / (1.0f + __expf(-x));
    if (act == ACT_SILU)    return x / (1.0f + __expf(-x));
    return x;
}

// ================= HMMA bf16 3-pass split GEMM =================
// C[M,N] = act(A*B^T), A ~ Ahi+Alo, B ~ Bhi+Blo; keep AhiBhi + AloBhi + AhiBlo.
// CTA 128 x BN_, KC=64, STAGES-deep cp.async pipeline, 8 warps (2 x 4).
// Warp tile: 64 x (BN_/4).
#define BM 128
#define KC 64
#define RSTR 144                       // smem row stride bytes (64 bf16 + 8 pad)

template<int BN_, int STAGES>
__global__ void __launch_bounds__(256)
gemm_hmma(const __nv_bfloat16* __restrict__ Ahi, const __nv_bfloat16* __restrict__ Alo,
          const __nv_bfloat16* __restrict__ Bhi, const __nv_bfloat16* __restrict__ Blo,
          int K, float* __restrict__ C, int ldc, unsigned actlut)
{
    constexpr int NJ = BN_ / 32;                    // n8 frags per warp (4 or 8)
    constexpr int SB = (256 + 2 * BN_) * RSTR;      // stage bytes
    constexpr uint32_t OFF_AH = 0;
    constexpr uint32_t OFF_AL = 128 * RSTR;
    constexpr uint32_t OFF_BH = 256 * RSTR;
    constexpr uint32_t OFF_BL = (256 + BN_) * RSTR;

    extern __shared__ char smem[];
    const uint32_t sbase = smem_u32(smem);
    const int tid  = threadIdx.x;
    const int bm   = blockIdx.y, bn = blockIdx.x;
    const int wid  = tid >> 5, lane = tid & 31;
    const int wm   = wid >> 2, wn = wid & 3;        // 2 x 4 warp grid

    const __nv_bfloat16* sA0 = Ahi + (size_t)bm * BM * K;
    const __nv_bfloat16* sA1 = Alo + (size_t)bm * BM * K;
    const __nv_bfloat16* sB0 = Bhi + (size_t)bn * BN_ * K;
    const __nv_bfloat16* sB1 = Blo + (size_t)bn * BN_ * K;

    const int lcol  = tid & 7;          // 16B chunk within 128B row
    const int lrow0 = tid >> 3;         // 0..31

    auto load_stage = [&](int s) {
        const uint32_t sb = sbase + (uint32_t)(s % STAGES) * SB + lcol * 16;
        const int k0 = s * KC + lcol * 8;
#pragma unroll
        for (int i = 0; i < 4; i++) {   // A tiles: 128 rows each
            int row = lrow0 + 32 * i;
            cp16(sb + OFF_AH + row * RSTR, sA0 + (size_t)row * K + k0);
            cp16(sb + OFF_AL + row * RSTR, sA1 + (size_t)row * K + k0);
        }
#pragma unroll
        for (int i = 0; i < BN_ / 32; i++) {  // B tiles: BN_ rows each
            int row = lrow0 + 32 * i;
            cp16(sb + OFF_BH + row * RSTR, sB0 + (size_t)row * K + k0);
            cp16(sb + OFF_BL + row * RSTR, sB1 + (size_t)row * K + k0);
        }
    };

    // ldmatrix lane address geometry
    const int quad = lane >> 3, r8 = lane & 7;
    const uint32_t aoff = (uint32_t)((wm * 64 + r8 + (quad & 1) * 8) * RSTR + (quad >> 1) * 16);
    const uint32_t boff = (uint32_t)((wn * (BN_ / 4) + r8 + (quad >> 1) * 8) * RSTR + (quad & 1) * 16);

    float acc[4][NJ][4];
#pragma unroll
    for (int mi = 0; mi < 4; mi++)
#pragma unroll
        for (int nj = 0; nj < NJ; nj++)
#pragma unroll
            for (int e = 0; e < 4; e++) acc[mi][nj][e] = 0.0f;

    const int ns = K / KC;
#pragma unroll
    for (int p = 0; p < STAGES - 1; p++) { load_stage(p); CP_COMMIT(); }

    for (int s = 0; s < ns; s++) {
        if (s + STAGES - 1 < ns) load_stage(s + STAGES - 1);
        CP_COMMIT();
        cp_wait<STAGES - 1>();
        __syncthreads();

        const uint32_t st = sbase + (uint32_t)(s % STAGES) * SB;
        const uint32_t aH = st + OFF_AH + aoff;
        const uint32_t aL = st + OFF_AL + aoff;
        const uint32_t bH = st + OFF_BH + boff;
        const uint32_t bL = st + OFF_BL + boff;

#pragma unroll
        for (int ks = 0; ks < 4; ks++) {
            const uint32_t kb = ks * 32;
            uint32_t afh[4][4], bf[NJ][2];

            // A-hi fragments (4 x m16)
#pragma unroll
            for (int mi = 0; mi < 4; mi++) ldm_x4(afh[mi], aH + mi * (16 * RSTR) + kb);
            // B-hi fragments (NJ x n8 via NJ/2 x4-loads)
#pragma unroll
            for (int t = 0; t < NJ / 2; t++) {
                uint32_t tt[4];
                ldm_x4(tt, bH + t * (16 * RSTR) + kb);
                bf[2 * t][0] = tt[0]; bf[2 * t][1] = tt[1];
                bf[2 * t + 1][0] = tt[2]; bf[2 * t + 1][1] = tt[3];
            }
            // pass 1: Ahi * Bhi
#pragma unroll
            for (int mi = 0; mi < 4; mi++)
#pragma unroll
                for (int nj = 0; nj < NJ; nj++) mma_bf16(acc[mi][nj], afh[mi], bf[nj]);
            // pass 2: Alo * Bhi (afl short-lived)
            {
                uint32_t afl[4][4];
#pragma unroll
                for (int mi = 0; mi < 4; mi++) ldm_x4(afl[mi], aL + mi * (16 * RSTR) + kb);
#pragma unroll
                for (int mi = 0; mi < 4; mi++)
#pragma unroll
                    for (int nj = 0; nj < NJ; nj++) mma_bf16(acc[mi][nj], afl[mi], bf[nj]);
            }
            // B-lo fragments (overwrite bf)
#pragma unroll
            for (int t = 0; t < NJ / 2; t++) {
                uint32_t tt[4];
                ldm_x4(tt, bL + t * (16 * RSTR) + kb);
                bf[2 * t][0] = tt[0]; bf[2 * t][1] = tt[1];
                bf[2 * t + 1][0] = tt[2]; bf[2 * t + 1][1] = tt[3];
            }
            // pass 3: Ahi * Blo
#pragma unroll
            for (int mi = 0; mi < 4; mi++)
#pragma unroll
                for (int nj = 0; nj < NJ; nj++) mma_bf16(acc[mi][nj], afh[mi], bf[nj]);
        }
        __syncthreads();
    }

    // ---- epilogue ----
    const int act  = (int)((actlut >> (((bn * BN_) >> 11) * 4)) & 15u);
    const int row0 = bm * BM + wm * 64 + (lane >> 2);
    const int col0 = bn * BN_ + wn * (BN_ / 4) + 2 * (lane & 3);
#pragma unroll
    for (int mi = 0; mi < 4; mi++) {
#pragma unroll
        for (int nj = 0; nj < NJ; nj++) {
            float2 v0, v1;
            v0.x = act_apply(acc[mi][nj][0], act);
            v0.y = act_apply(acc[mi][nj][1], act);
            v1.x = act_apply(acc[mi][nj][2], act);
            v1.y = act_apply(acc[mi][nj][3], act);
            size_t base = (size_t)(row0 + mi * 16) * ldc + col0 + nj * 8;
            *(float2*)(C + base)                   = v0;
            *(float2*)(C + base + (size_t)8 * ldc) = v1;
        }
    }
}

// ================= conversion kernels =================
__device__ __forceinline__ void split_bf16(float v, __nv_bfloat16& hi, __nv_bfloat16& lo) {
    hi = __float2bfloat16(v);
    lo = __float2bfloat16(v - __bfloat162float(hi));
}

__global__ void conv_x_kernel(const float* __restrict__ x,
                              __nv_bfloat16* __restrict__ hi, __nv_bfloat16* __restrict__ lo) {
    size_t i = (size_t)blockIdx.x * blockDim.x + threadIdx.x;
    split_bf16(x[i], hi[i], lo[i]);
}

__global__ void conv_w6_kernel(const float* __restrict__ w0, const float* __restrict__ w1,
                               const float* __restrict__ w2, const float* __restrict__ w3,
                               const float* __restrict__ w4, const float* __restrict__ w5,
                               __nv_bfloat16* __restrict__ hi, __nv_bfloat16* __restrict__ lo) {
    size_t i = (size_t)blockIdx.x * blockDim.x + threadIdx.x;     // [0, 12288*1024)
    int n = (int)(i >> 10);
    int k = (int)(i & 1023);
    int w = n >> 11, r = n & 2047;
    const float* src = (w == 0) ? w0 : (w == 1) ? w1 : (w == 2) ? w2
                     : (w == 3) ? w3 : (w == 4) ? w4 : w5;
    split_bf16(src[(size_t)r * 1024 + k], hi[i], lo[i]);
}

__global__ void conv_wout_kernel(const float* __restrict__ Wro, const float* __restrict__ Wd,
                                 __nv_bfloat16* __restrict__ hi, __nv_bfloat16* __restrict__ lo) {
    size_t i = (size_t)blockIdx.x * blockDim.x + threadIdx.x;     // [0, 1024*4096)
    int h = (int)(i >> 12);
    int j = (int)(i & 4095);
    float v = (j < 2048) ? Wro[(size_t)h * 2048 + j] : Wd[(size_t)h * 2048 + (j - 2048)];
    split_bf16(v, hi[i], lo[i]);
}

// ================= scan (two-level, chunked) =================
// P cols: f[0:2048) g[2048:4096) c[4096:6144) q[6144:8192) up[8192:10240) gate_silu[10240:12288)
__global__ void scanA_kernel(const float* __restrict__ P,
                             float* __restrict__ Fc, float* __restrict__ Gc) {
    int r  = blockIdx.x * blockDim.x + threadIdx.x;
    int bc = blockIdx.y;
    int b = bc >> 6, ch = bc & 63;
    const float* row = P + (size_t)(b * SDIM + ch * CH) * NPROJ;
    float F = 1.0f, G = 0.0f;
#pragma unroll 4
    for (int t = 0; t < CH; t++) {
        float f = row[r];
        float g = row[2048 + r];
        float c = row[4096 + r];
        G = fmaf(f, G, g * c);
        F *= f;
        row += NPROJ;
    }
    Fc[(size_t)bc * RDIM + r] = F;
    Gc[(size_t)bc * RDIM + r] = G;
}

__global__ void scanB_kernel(const float* __restrict__ Fc, const float* __restrict__ Gc,
                             const float* __restrict__ init, float* __restrict__ Sc) {
    int i = blockIdx.x * blockDim.x + threadIdx.x;
    int b = i >> 11, r = i & 2047;
    float state = init[r];
    for (int ch = 0; ch < NCH; ch++) {
        size_t idx = (size_t)(b * NCH + ch) * RDIM + r;
        Sc[idx] = state;
        state = fmaf(Fc[idx], state, Gc[idx]);
    }
}

__global__ void scanC_kernel(const float* __restrict__ P, const float* __restrict__ Sc,
                             __nv_bfloat16* __restrict__ a2hi, __nv_bfloat16* __restrict__ a2lo) {
    int r  = blockIdx.x * blockDim.x + threadIdx.x;
    int bc = blockIdx.y;
    int b = bc >> 6, ch = bc & 63;
    int m0 = b * SDIM + ch * CH;
    const float* row = P + (size_t)m0 * NPROJ;
    float state = Sc[(size_t)bc * RDIM + r];
#pragma unroll 4
    for (int t = 0; t < CH; t++) {
        float f = row[r];
        float g = row[2048 + r];
        float c = row[4096 + r];
        float q = row[6144 + r];
        state = fmaf(f, state, g * c);
        float z = q * state;
        float ro = z / (1.0f + __expf(-z));
        __nv_bfloat16 hi, lo;
        split_bf16(ro, hi, lo);
        size_t oi = (size_t)(m0 + t) * KOUT + r;
        a2hi[oi] = hi;
        a2lo[oi] = lo;
        row += NPROJ;
    }
}

__global__ void hcomb_kernel(const float* __restrict__ P,
                             __nv_bfloat16* __restrict__ a2hi, __nv_bfloat16* __restrict__ a2lo) {
    size_t i = (size_t)blockIdx.x * blockDim.x + threadIdx.x;
    int m = (int)(i >> 11);
    int l = (int)(i & 2047);
    const float* row = P + (size_t)m * NPROJ;
    float h = row[8192 + l] * row[10240 + l];
    __nv_bfloat16 hi, lo;
    split_bf16(h, hi, lo);
    size_t oi = (size_t)m * KOUT + 2048 + l;
    a2hi[oi] = hi;
    a2lo[oi] = lo;
}

// ================= launch =================
extern "C" void kernel_launch(void* const* d_in, const int* in_sizes, int n_in,
                              void* d_out, int out_size)
{
    const float* x    = (const float*)d_in[0];
    const float* Wf   = (const float*)d_in[1];
    const float* Wi   = (const float*)d_in[2];
    const float* Wv   = (const float*)d_in[3];
    const float* Wq   = (const float*)d_in[4];
    const float* Wro  = (const float*)d_in[5];
    const float* Wup  = (const float*)d_in[6];
    const float* Wg   = (const float*)d_in[7];
    const float* Wd   = (const float*)d_in[8];
    const float* init = (const float*)d_in[9];
    float* out = (float*)d_out;

    float *pP, *pFc, *pGc, *pSc;
    __nv_bfloat16 *pxhi, *pxlo, *pw6hi, *pw6lo, *pwohi, *pwolo, *pa2hi, *pa2lo;
    cudaGetSymbolAddress((void**)&pP,    g_P);
    cudaGetSymbolAddress((void**)&pxhi,  g_xhi);
    cudaGetSymbolAddress((void**)&pxlo,  g_xlo);
    cudaGetSymbolAddress((void**)&pw6hi, g_w6hi);
    cudaGetSymbolAddress((void**)&pw6lo, g_w6lo);
    cudaGetSymbolAddress((void**)&pwohi, g_wohi);
    cudaGetSymbolAddress((void**)&pwolo, g_wolo);
    cudaGetSymbolAddress((void**)&pa2hi, g_a2hi);
    cudaGetSymbolAddress((void**)&pa2lo, g_a2lo);
    cudaGetSymbolAddress((void**)&pFc,   g_Fc);
    cudaGetSymbolAddress((void**)&pGc,   g_Gc);
    cudaGetSymbolAddress((void**)&pSc,   g_Sc);

    // smem sizes: BN=256/2-stage: (256+512)*144*2 = 221184
    //             BN=128/3-stage: (256+256)*144*3 = 221184
    const int SMEM1 = (256 + 512) * RSTR * 2;
    const int SMEM2 = (256 + 256) * RSTR * 3;
    cudaFuncSetAttribute(gemm_hmma<256, 2>, cudaFuncAttributeMaxDynamicSharedMemorySize, SMEM1);
    cudaFuncSetAttribute(gemm_hmma<128, 3>, cudaFuncAttributeMaxDynamicSharedMemorySize, SMEM2);

    // conversions
    conv_x_kernel   <<<(MDIM * HDIM) / 256, 256>>>(x, pxhi, pxlo);
    conv_w6_kernel  <<<(NPROJ * HDIM) / 256, 256>>>(Wf, Wi, Wv, Wq, Wup, Wg, pw6hi, pw6lo);
    conv_wout_kernel<<<(HDIM * KOUT) / 256, 256>>>(Wro, Wd, pwohi, pwolo);

    // GEMM1: P = act( x @ W6^T ); acts per 2048-col block: tanh,sig,silu,none,none,silu
    {
        dim3 grid(NPROJ / 256, MDIM / BM);   // (48, 64)
        gemm_hmma<256, 2><<<grid, 256, SMEM1>>>(pxhi, pxlo, pw6hi, pw6lo, HDIM, pP, NPROJ, 0x300321u);
    }

    // scan
    {
        dim3 gA(RDIM / 256, 4 * NCH);
        scanA_kernel<<<gA, 256>>>(pP, pFc, pGc);
        scanB_kernel<<<32, 256>>>(pFc, pGc, init, pSc);
        scanC_kernel<<<gA, 256>>>(pP, pSc, pa2hi, pa2lo);
        hcomb_kernel<<<(MDIM * RDIM) / 256, 256>>>(pP, pa2hi, pa2lo);
    }

    // GEMM2: out = [ro | h] @ [Wro | Wd]^T
    {
        dim3 grid(HDIM / 128, MDIM / BM);    // (8, 64)
        gemm_hmma<128, 3><<<grid, 256, SMEM2>>>(pa2hi, pa2lo, pwohi, pwolo, KOUT, out, HDIM, 0u);
    }
}

// round 5
// speedup vs baseline: 3.0572x; 1.0108x over previous
#include <cuda_runtime.h>
#include <cuda_bf16.h>
#include <stdint.h>
#include <math.h>

// ---------------- problem dims ----------------
#define MDIM 8192      // B*S
#define HDIM 1024
#define RDIM 2048
#define SDIM 2048
#define NPROJ 12288    // 6 * 2048 stacked projection outputs
#define KOUT 4096      // R + L for the output GEMM
#define NCH 64         // scan chunks
#define CH 32          // tokens per chunk

// ---------------- scratch (device globals) ----------------
__device__ float          g_P   [(size_t)MDIM * NPROJ];
__device__ __nv_bfloat16  g_xhi [(size_t)MDIM * HDIM];
__device__ __nv_bfloat16  g_xlo [(size_t)MDIM * HDIM];
__device__ __nv_bfloat16  g_w6hi[(size_t)NPROJ * HDIM];
__device__ __nv_bfloat16  g_w6lo[(size_t)NPROJ * HDIM];
__device__ __nv_bfloat16  g_wohi[(size_t)HDIM * KOUT];
__device__ __nv_bfloat16  g_wolo[(size_t)HDIM * KOUT];
__device__ __nv_bfloat16  g_a2hi[(size_t)MDIM * KOUT];
__device__ __nv_bfloat16  g_a2lo[(size_t)MDIM * KOUT];
__device__ float          g_Fc  [(size_t)4 * NCH * RDIM];
__device__ float          g_Gc  [(size_t)4 * NCH * RDIM];
__device__ float          g_Sc  [(size_t)4 * NCH * RDIM];

// ---------------- helpers ----------------
__device__ __forceinline__ uint32_t smem_u32(const void* p) {
    uint32_t a;
    asm("{ .reg .u64 t; cvta.to.shared.u64 t, %1; cvt.u32.u64 %0, t; }" : "=r"(a) : "l"(p));
    return a;
}
__device__ __forceinline__ void cp16(uint32_t s, const void* g) {
    asm volatile("cp.async.cg.shared.global [%0], [%1], 16;" :: "r"(s), "l"(g));
}
#define CP_COMMIT() asm volatile("cp.async.commit_group;" ::: "memory")
template<int N> __device__ __forceinline__ void cp_wait() {
    asm volatile("cp.async.wait_group %0;" :: "n"(N) : "memory");
}

__device__ __forceinline__ void ldm_x4(uint32_t (&d)[4], uint32_t a) {
    asm volatile("ldmatrix.sync.aligned.m8n8.x4.shared.b16 {%0,%1,%2,%3}, [%4];"
        : "=r"(d[0]), "=r"(d[1]), "=r"(d[2]), "=r"(d[3]) : "r"(a));
}
__device__ __forceinline__ void mma_bf16(float (&c)[4], const uint32_t (&a)[4], const uint32_t* b) {
    asm volatile("mma.sync.aligned.m16n8k16.row.col.f32.bf16.bf16.f32 "
        "{%0,%1,%2,%3}, {%4,%5,%6,%7}, {%8,%9}, {%0,%1,%2,%3};"
        : "+f"(c[0]), "+f"(c[1]), "+f"(c[2]), "+f"(c[3])
        : "r"(a[0]), "r"(a[1]), "r"(a[2]), "r"(a[3]), "r"(b[0]), "r"(b[1]));
}

// ---------------- activation ----------------
#define ACT_NONE 0
#define ACT_TANH 1
#define ACT_SIGMOID 2
#define ACT_SILU 3
__device__ __forceinline__ float act_apply(float x, int act) {
    if (act == ACT_TANH)    return tanhf(x);
    if (act == ACT_SIGMOID) return 1.0f / (1.0f + __expf(-x));
    if (act == ACT_SILU)    return x / (1.0f + __expf(-x));
    return x;
}

// ================= HMMA bf16 3-pass split GEMM =================
// C[M,N] = act(A*B^T), A ~ Ahi+Alo, B ~ Bhi+Blo; keep AhiBhi + AloBhi + AhiBlo.
// CTA 64 x 128, 128 threads (4 warps, each 64x32), KC=64, 2-stage cp.async
// pipeline, 110.6KB smem -> 2 CTAs/SM for cross-CTA latency hiding.
#define BM 64
#define BN 128
#define KC 64
#define RSTR 144                        // smem row stride bytes (64 bf16 + 8 pad)
#define OFF_AH 0
#define OFF_AL (64 * RSTR)
#define OFF_BH (128 * RSTR)
#define OFF_BL (256 * RSTR)
#define SB (384 * RSTR)                 // 55296 bytes per stage
#define GEMM_SMEM (2 * SB)              // 110592

__global__ void __launch_bounds__(128, 2)
gemm_hmma(const __nv_bfloat16* __restrict__ Ahi, const __nv_bfloat16* __restrict__ Alo,
          const __nv_bfloat16* __restrict__ Bhi, const __nv_bfloat16* __restrict__ Blo,
          int K, float* __restrict__ C, int ldc, unsigned actlut)
{
    extern __shared__ char smem[];
    const uint32_t sbase = smem_u32(smem);
    const int tid  = threadIdx.x;
    const int bm   = blockIdx.y, bn = blockIdx.x;
    const int wn   = tid >> 5, lane = tid & 31;     // 4 warps in 1x4

    const __nv_bfloat16* sA0 = Ahi + (size_t)bm * BM * K;
    const __nv_bfloat16* sA1 = Alo + (size_t)bm * BM * K;
    const __nv_bfloat16* sB0 = Bhi + (size_t)bn * BN * K;
    const __nv_bfloat16* sB1 = Blo + (size_t)bn * BN * K;

    const int lcol  = tid & 7;          // 16B chunk within 128B row
    const int lrow0 = tid >> 3;         // 0..15

    auto load_stage = [&](int s) {
        const uint32_t sb = sbase + (uint32_t)(s & 1) * SB + lcol * 16;
        const int k0 = s * KC + lcol * 8;
#pragma unroll
        for (int i = 0; i < 4; i++) {   // A hi/lo: 64 rows each
            int row = lrow0 + 16 * i;
            cp16(sb + OFF_AH + row * RSTR, sA0 + (size_t)row * K + k0);
            cp16(sb + OFF_AL + row * RSTR, sA1 + (size_t)row * K + k0);
        }
#pragma unroll
        for (int i = 0; i < 8; i++) {   // B hi/lo: 128 rows each
            int row = lrow0 + 16 * i;
            cp16(sb + OFF_BH + row * RSTR, sB0 + (size_t)row * K + k0);
            cp16(sb + OFF_BL + row * RSTR, sB1 + (size_t)row * K + k0);
        }
    };

    // ldmatrix lane address geometry
    const int quad = lane >> 3, r8 = lane & 7;
    const uint32_t aoff = (uint32_t)((r8 + (quad & 1) * 8) * RSTR + (quad >> 1) * 16);
    const uint32_t boff = (uint32_t)((wn * 32 + r8 + (quad >> 1) * 8) * RSTR + (quad & 1) * 16);

    float acc[4][4][4];
#pragma unroll
    for (int mi = 0; mi < 4; mi++)
#pragma unroll
        for (int nj = 0; nj < 4; nj++)
#pragma unroll
            for (int e = 0; e < 4; e++) acc[mi][nj][e] = 0.0f;

    const int ns = K / KC;
    load_stage(0); CP_COMMIT();

    for (int s = 0; s < ns; s++) {
        if (s + 1 < ns) load_stage(s + 1);
        CP_COMMIT();
        cp_wait<1>();
        __syncthreads();

        const uint32_t st = sbase + (uint32_t)(s & 1) * SB;
        const uint32_t aH = st + OFF_AH + aoff;
        const uint32_t aL = st + OFF_AL + aoff;
        const uint32_t bH = st + OFF_BH + boff;
        const uint32_t bL = st + OFF_BL + boff;

#pragma unroll
        for (int ks = 0; ks < 4; ks++) {
            const uint32_t kb = ks * 32;
            uint32_t afh[4][4], bf[4][2];

            // A-hi fragments (4 x m16)
#pragma unroll
            for (int mi = 0; mi < 4; mi++) ldm_x4(afh[mi], aH + mi * (16 * RSTR) + kb);
            // B-hi fragments (4 x n8 via 2 x4-loads)
#pragma unroll
            for (int t = 0; t < 2; t++) {
                uint32_t tt[4];
                ldm_x4(tt, bH + t * (16 * RSTR) + kb);
                bf[2 * t][0] = tt[0]; bf[2 * t][1] = tt[1];
                bf[2 * t + 1][0] = tt[2]; bf[2 * t + 1][1] = tt[3];
            }
            // pass 1: Ahi * Bhi
#pragma unroll
            for (int mi = 0; mi < 4; mi++)
#pragma unroll
                for (int nj = 0; nj < 4; nj++) mma_bf16(acc[mi][nj], afh[mi], bf[nj]);
            // pass 2: Alo * Bhi (afl short-lived)
            {
                uint32_t afl[4][4];
#pragma unroll
                for (int mi = 0; mi < 4; mi++) ldm_x4(afl[mi], aL + mi * (16 * RSTR) + kb);
#pragma unroll
                for (int mi = 0; mi < 4; mi++)
#pragma unroll
                    for (int nj = 0; nj < 4; nj++) mma_bf16(acc[mi][nj], afl[mi], bf[nj]);
            }
            // B-lo fragments (overwrite bf)
#pragma unroll
            for (int t = 0; t < 2; t++) {
                uint32_t tt[4];
                ldm_x4(tt, bL + t * (16 * RSTR) + kb);
                bf[2 * t][0] = tt[0]; bf[2 * t][1] = tt[1];
                bf[2 * t + 1][0] = tt[2]; bf[2 * t + 1][1] = tt[3];
            }
            // pass 3: Ahi * Blo
#pragma unroll
            for (int mi = 0; mi < 4; mi++)
#pragma unroll
                for (int nj = 0; nj < 4; nj++) mma_bf16(acc[mi][nj], afh[mi], bf[nj]);
        }
        __syncthreads();
    }

    // ---- epilogue ----
    const int act  = (int)((actlut >> (((bn * BN) >> 11) * 4)) & 15u);
    const int row0 = bm * BM + (lane >> 2);
    const int col0 = bn * BN + wn * 32 + 2 * (lane & 3);
#pragma unroll
    for (int mi = 0; mi < 4; mi++) {
#pragma unroll
        for (int nj = 0; nj < 4; nj++) {
            float2 v0, v1;
            v0.x = act_apply(acc[mi][nj][0], act);
            v0.y = act_apply(acc[mi][nj][1], act);
            v1.x = act_apply(acc[mi][nj][2], act);
            v1.y = act_apply(acc[mi][nj][3], act);
            size_t base = (size_t)(row0 + mi * 16) * ldc + col0 + nj * 8;
            *(float2*)(C + base)                   = v0;
            *(float2*)(C + base + (size_t)8 * ldc) = v1;
        }
    }
}

// ================= conversion kernels =================
__device__ __forceinline__ void split_bf16(float v, __nv_bfloat16& hi, __nv_bfloat16& lo) {
    hi = __float2bfloat16(v);
    lo = __float2bfloat16(v - __bfloat162float(hi));
}

__global__ void conv_x_kernel(const float* __restrict__ x,
                              __nv_bfloat16* __restrict__ hi, __nv_bfloat16* __restrict__ lo) {
    size_t i = (size_t)blockIdx.x * blockDim.x + threadIdx.x;
    split_bf16(x[i], hi[i], lo[i]);
}

__global__ void conv_w6_kernel(const float* __restrict__ w0, const float* __restrict__ w1,
                               const float* __restrict__ w2, const float* __restrict__ w3,
                               const float* __restrict__ w4, const float* __restrict__ w5,
                               __nv_bfloat16* __restrict__ hi, __nv_bfloat16* __restrict__ lo) {
    size_t i = (size_t)blockIdx.x * blockDim.x + threadIdx.x;     // [0, 12288*1024)
    int n = (int)(i >> 10);
    int k = (int)(i & 1023);
    int w = n >> 11, r = n & 2047;
    const float* src = (w == 0) ? w0 : (w == 1) ? w1 : (w == 2) ? w2
                     : (w == 3) ? w3 : (w == 4) ? w4 : w5;
    split_bf16(src[(size_t)r * 1024 + k], hi[i], lo[i]);
}

__global__ void conv_wout_kernel(const float* __restrict__ Wro, const float* __restrict__ Wd,
                                 __nv_bfloat16* __restrict__ hi, __nv_bfloat16* __restrict__ lo) {
    size_t i = (size_t)blockIdx.x * blockDim.x + threadIdx.x;     // [0, 1024*4096)
    int h = (int)(i >> 12);
    int j = (int)(i & 4095);
    float v = (j < 2048) ? Wro[(size_t)h * 2048 + j] : Wd[(size_t)h * 2048 + (j - 2048)];
    split_bf16(v, hi[i], lo[i]);
}

// ================= scan (two-level, chunked) =================
// P cols: f[0:2048) g[2048:4096) c[4096:6144) q[6144:8192) up[8192:10240) gate_silu[10240:12288)
__global__ void scanA_kernel(const float* __restrict__ P,
                             float* __restrict__ Fc, float* __restrict__ Gc) {
    int r  = blockIdx.x * blockDim.x + threadIdx.x;
    int bc = blockIdx.y;
    int b = bc >> 6, ch = bc & 63;
    const float* row = P + (size_t)(b * SDIM + ch * CH) * NPROJ;
    float F = 1.0f, G = 0.0f;
#pragma unroll 4
    for (int t = 0; t < CH; t++) {
        float f = row[r];
        float g = row[2048 + r];
        float c = row[4096 + r];
        G = fmaf(f, G, g * c);
        F *= f;
        row += NPROJ;
    }
    Fc[(size_t)bc * RDIM + r] = F;
    Gc[(size_t)bc * RDIM + r] = G;
}

__global__ void scanB_kernel(const float* __restrict__ Fc, const float* __restrict__ Gc,
                             const float* __restrict__ init, float* __restrict__ Sc) {
    int i = blockIdx.x * blockDim.x + threadIdx.x;
    int b = i >> 11, r = i & 2047;
    float state = init[r];
    for (int ch = 0; ch < NCH; ch++) {
        size_t idx = (size_t)(b * NCH + ch) * RDIM + r;
        Sc[idx] = state;
        state = fmaf(Fc[idx], state, Gc[idx]);
    }
}

__global__ void scanC_kernel(const float* __restrict__ P, const float* __restrict__ Sc,
                             __nv_bfloat16* __restrict__ a2hi, __nv_bfloat16* __restrict__ a2lo) {
    int r  = blockIdx.x * blockDim.x + threadIdx.x;
    int bc = blockIdx.y;
    int b = bc >> 6, ch = bc & 63;
    int m0 = b * SDIM + ch * CH;
    const float* row = P + (size_t)m0 * NPROJ;
    float state = Sc[(size_t)bc * RDIM + r];
#pragma unroll 4
    for (int t = 0; t < CH; t++) {
        float f = row[r];
        float g = row[2048 + r];
        float c = row[4096 + r];
        float q = row[6144 + r];
        state = fmaf(f, state, g * c);
        float z = q * state;
        float ro = z / (1.0f + __expf(-z));
        __nv_bfloat16 hi, lo;
        split_bf16(ro, hi, lo);
        size_t oi = (size_t)(m0 + t) * KOUT + r;
        a2hi[oi] = hi;
        a2lo[oi] = lo;
        row += NPROJ;
    }
}

__global__ void hcomb_kernel(const float* __restrict__ P,
                             __nv_bfloat16* __restrict__ a2hi, __nv_bfloat16* __restrict__ a2lo) {
    size_t i = (size_t)blockIdx.x * blockDim.x + threadIdx.x;
    int m = (int)(i >> 11);
    int l = (int)(i & 2047);
    const float* row = P + (size_t)m * NPROJ;
    float h = row[8192 + l] * row[10240 + l];
    __nv_bfloat16 hi, lo;
    split_bf16(h, hi, lo);
    size_t oi = (size_t)m * KOUT + 2048 + l;
    a2hi[oi] = hi;
    a2lo[oi] = lo;
}

// ================= launch =================
extern "C" void kernel_launch(void* const* d_in, const int* in_sizes, int n_in,
                              void* d_out, int out_size)
{
    const float* x    = (const float*)d_in[0];
    const float* Wf   = (const float*)d_in[1];
    const float* Wi   = (const float*)d_in[2];
    const float* Wv   = (const float*)d_in[3];
    const float* Wq   = (const float*)d_in[4];
    const float* Wro  = (const float*)d_in[5];
    const float* Wup  = (const float*)d_in[6];
    const float* Wg   = (const float*)d_in[7];
    const float* Wd   = (const float*)d_in[8];
    const float* init = (const float*)d_in[9];
    float* out = (float*)d_out;

    float *pP, *pFc, *pGc, *pSc;
    __nv_bfloat16 *pxhi, *pxlo, *pw6hi, *pw6lo, *pwohi, *pwolo, *pa2hi, *pa2lo;
    cudaGetSymbolAddress((void**)&pP,    g_P);
    cudaGetSymbolAddress((void**)&pxhi,  g_xhi);
    cudaGetSymbolAddress((void**)&pxlo,  g_xlo);
    cudaGetSymbolAddress((void**)&pw6hi, g_w6hi);
    cudaGetSymbolAddress((void**)&pw6lo, g_w6lo);
    cudaGetSymbolAddress((void**)&pwohi, g_wohi);
    cudaGetSymbolAddress((void**)&pwolo, g_wolo);
    cudaGetSymbolAddress((void**)&pa2hi, g_a2hi);
    cudaGetSymbolAddress((void**)&pa2lo, g_a2lo);
    cudaGetSymbolAddress((void**)&pFc,   g_Fc);
    cudaGetSymbolAddress((void**)&pGc,   g_Gc);
    cudaGetSymbolAddress((void**)&pSc,   g_Sc);

    cudaFuncSetAttribute(gemm_hmma, cudaFuncAttributeMaxDynamicSharedMemorySize, GEMM_SMEM);

    // conversions
    conv_x_kernel   <<<(MDIM * HDIM) / 256, 256>>>(x, pxhi, pxlo);
    conv_w6_kernel  <<<(NPROJ * HDIM) / 256, 256>>>(Wf, Wi, Wv, Wq, Wup, Wg, pw6hi, pw6lo);
    conv_wout_kernel<<<(HDIM * KOUT) / 256, 256>>>(Wro, Wd, pwohi, pwolo);

    // GEMM1: P = act( x @ W6^T ); acts per 2048-col block: tanh,sig,silu,none,none,silu
    {
        dim3 grid(NPROJ / BN, MDIM / BM);   // (96, 128)
        gemm_hmma<<<grid, 128, GEMM_SMEM>>>(pxhi, pxlo, pw6hi, pw6lo, HDIM, pP, NPROJ, 0x300321u);
    }

    // scan
    {
        dim3 gA(RDIM / 256, 4 * NCH);
        scanA_kernel<<<gA, 256>>>(pP, pFc, pGc);
        scanB_kernel<<<32, 256>>>(pFc, pGc, init, pSc);
        scanC_kernel<<<gA, 256>>>(pP, pSc, pa2hi, pa2lo);
        hcomb_kernel<<<(MDIM * RDIM) / 256, 256>>>(pP, pa2hi, pa2lo);
    }

    // GEMM2: out = [ro | h] @ [Wro | Wd]^T
    {
        dim3 grid(HDIM / BN, MDIM / BM);    // (8, 128)
        gemm_hmma<<<grid, 128, GEMM_SMEM>>>(pa2hi, pa2lo, pwohi, pwolo, KOUT, out, HDIM, 0u);
    }
}

// round 6
// speedup vs baseline: 3.1876x; 1.0427x over previous
#include <cuda_runtime.h>
#include <cuda_bf16.h>
#include <stdint.h>
#include <math.h>

// ---------------- problem dims ----------------
#define MDIM 8192      // B*S
#define HDIM 1024
#define RDIM 2048
#define SDIM 2048
#define NPROJ 12288    // 6 * 2048 stacked projection outputs
#define KOUT 4096      // R + L for the output GEMM
#define NCH 64         // scan chunks
#define CH 32          // tokens per chunk

// ---------------- scratch (device globals) ----------------
__device__ float          g_P   [(size_t)MDIM * NPROJ];
__device__ __nv_bfloat16  g_xhi [(size_t)MDIM * HDIM];
__device__ __nv_bfloat16  g_xlo [(size_t)MDIM * HDIM];
__device__ __nv_bfloat16  g_w6hi[(size_t)NPROJ * HDIM];
__device__ __nv_bfloat16  g_w6lo[(size_t)NPROJ * HDIM];
__device__ __nv_bfloat16  g_wohi[(size_t)HDIM * KOUT];
__device__ __nv_bfloat16  g_wolo[(size_t)HDIM * KOUT];
__device__ __nv_bfloat16  g_a2hi[(size_t)MDIM * KOUT];
__device__ __nv_bfloat16  g_a2lo[(size_t)MDIM * KOUT];
__device__ float          g_Fc  [(size_t)4 * NCH * RDIM];
__device__ float          g_Gc  [(size_t)4 * NCH * RDIM];
__device__ float          g_Sc  [(size_t)4 * NCH * RDIM];

// ---------------- helpers ----------------
__device__ __forceinline__ uint32_t smem_u32(const void* p) {
    uint32_t a;
    asm("{ .reg .u64 t; cvta.to.shared.u64 t, %1; cvt.u32.u64 %0, t; }" : "=r"(a) : "l"(p));
    return a;
}
__device__ __forceinline__ void cp16(uint32_t s, const void* g) {
    asm volatile("cp.async.cg.shared.global [%0], [%1], 16;" :: "r"(s), "l"(g));
}
#define CP_COMMIT() asm volatile("cp.async.commit_group;" ::: "memory")
template<int N> __device__ __forceinline__ void cp_wait() {
    asm volatile("cp.async.wait_group %0;" :: "n"(N) : "memory");
}

__device__ __forceinline__ void ldm_x4(uint32_t (&d)[4], uint32_t a) {
    asm volatile("ldmatrix.sync.aligned.m8n8.x4.shared.b16 {%0,%1,%2,%3}, [%4];"
        : "=r"(d[0]), "=r"(d[1]), "=r"(d[2]), "=r"(d[3]) : "r"(a));
}
__device__ __forceinline__ void mma_bf16(float (&c)[4], const uint32_t (&a)[4], const uint32_t* b) {
    asm volatile("mma.sync.aligned.m16n8k16.row.col.f32.bf16.bf16.f32 "
        "{%0,%1,%2,%3}, {%4,%5,%6,%7}, {%8,%9}, {%0,%1,%2,%3};"
        : "+f"(c[0]), "+f"(c[1]), "+f"(c[2]), "+f"(c[3])
        : "r"(a[0]), "r"(a[1]), "r"(a[2]), "r"(a[3]), "r"(b[0]), "r"(b[1]));
}

// ---------------- activation ----------------
#define ACT_NONE 0
#define ACT_TANH 1
#define ACT_SIGMOID 2
#define ACT_SILU 3
__device__ __forceinline__ float act_apply(float x, int act) {
    if (act == ACT_TANH)    return tanhf(x);
    if (act == ACT_SIGMOID) return 1.0f / (1.0f + __expf(-x));
    if (act == ACT_SILU)    return x / (1.0f + __expf(-x));
    return x;
}

// ================= HMMA bf16 3-pass split GEMM =================
// C[M,N] = act(A*B^T), A ~ Ahi+Alo, B ~ Bhi+Blo; keep AhiBhi + AloBhi + AhiBlo.
// CTA 64 x 128, 128 threads (4 warps, each 64x32), KC=32, 2-stage cp.async,
// 60KB smem and <=170 regs -> 3 CTAs/SM (12 warps, 3 independent barrier
// domains per SMSP) for HMMA latency hiding.
#define BM 64
#define BN 128
#define KC 32
#define RSTR 80                         // 64B row + 16B pad (20-bank stride,
                                        // conflict-free ldmatrix groups)
#define OFF_AH 0
#define OFF_AL (64 * RSTR)
#define OFF_BH (128 * RSTR)
#define OFF_BL (256 * RSTR)
#define SB (384 * RSTR)                 // 30720 bytes per stage
#define GEMM_SMEM (2 * SB)              // 61440

__global__ void __launch_bounds__(128, 3)
gemm_hmma(const __nv_bfloat16* __restrict__ Ahi, const __nv_bfloat16* __restrict__ Alo,
          const __nv_bfloat16* __restrict__ Bhi, const __nv_bfloat16* __restrict__ Blo,
          int K, float* __restrict__ C, int ldc, unsigned actlut)
{
    extern __shared__ char smem[];
    const uint32_t sbase = smem_u32(smem);
    const int tid  = threadIdx.x;
    const int bm   = blockIdx.y, bn = blockIdx.x;
    const int wn   = tid >> 5, lane = tid & 31;     // 4 warps in 1x4

    const __nv_bfloat16* sA0 = Ahi + (size_t)bm * BM * K;
    const __nv_bfloat16* sA1 = Alo + (size_t)bm * BM * K;
    const __nv_bfloat16* sB0 = Bhi + (size_t)bn * BN * K;
    const __nv_bfloat16* sB1 = Blo + (size_t)bn * BN * K;

    const int lcol  = tid & 3;          // 16B chunk within 64B row
    const int lrow0 = tid >> 2;         // 0..31

    auto load_stage = [&](int s) {
        const uint32_t sb = sbase + (uint32_t)(s & 1) * SB + lcol * 16;
        const int k0 = s * KC + lcol * 8;
#pragma unroll
        for (int i = 0; i < 2; i++) {   // A hi/lo: 64 rows each
            int row = lrow0 + 32 * i;
            cp16(sb + OFF_AH + row * RSTR, sA0 + (size_t)row * K + k0);
            cp16(sb + OFF_AL + row * RSTR, sA1 + (size_t)row * K + k0);
        }
#pragma unroll
        for (int i = 0; i < 4; i++) {   // B hi/lo: 128 rows each
            int row = lrow0 + 32 * i;
            cp16(sb + OFF_BH + row * RSTR, sB0 + (size_t)row * K + k0);
            cp16(sb + OFF_BL + row * RSTR, sB1 + (size_t)row * K + k0);
        }
    };

    // ldmatrix lane address geometry
    const int quad = lane >> 3, r8 = lane & 7;
    const uint32_t aoff = (uint32_t)((r8 + (quad & 1) * 8) * RSTR + (quad >> 1) * 16);
    const uint32_t boff = (uint32_t)((wn * 32 + r8 + (quad >> 1) * 8) * RSTR + (quad & 1) * 16);

    float acc[4][4][4];
#pragma unroll
    for (int mi = 0; mi < 4; mi++)
#pragma unroll
        for (int nj = 0; nj < 4; nj++)
#pragma unroll
            for (int e = 0; e < 4; e++) acc[mi][nj][e] = 0.0f;

    const int ns = K / KC;
    load_stage(0); CP_COMMIT();

    for (int s = 0; s < ns; s++) {
        if (s + 1 < ns) load_stage(s + 1);
        CP_COMMIT();
        cp_wait<1>();
        __syncthreads();

        const uint32_t st = sbase + (uint32_t)(s & 1) * SB;
        const uint32_t aH = st + OFF_AH + aoff;
        const uint32_t aL = st + OFF_AL + aoff;
        const uint32_t bH = st + OFF_BH + boff;
        const uint32_t bL = st + OFF_BL + boff;

#pragma unroll
        for (int ks = 0; ks < 2; ks++) {
            const uint32_t kb = ks * 32;
            uint32_t afh[4][4], bf[4][2];

            // A-hi fragments (4 x m16)
#pragma unroll
            for (int mi = 0; mi < 4; mi++) ldm_x4(afh[mi], aH + mi * (16 * RSTR) + kb);
            // B-hi fragments (4 x n8 via 2 x4-loads)
#pragma unroll
            for (int t = 0; t < 2; t++) {
                uint32_t tt[4];
                ldm_x4(tt, bH + t * (16 * RSTR) + kb);
                bf[2 * t][0] = tt[0]; bf[2 * t][1] = tt[1];
                bf[2 * t + 1][0] = tt[2]; bf[2 * t + 1][1] = tt[3];
            }
            // pass 1: Ahi * Bhi
#pragma unroll
            for (int mi = 0; mi < 4; mi++)
#pragma unroll
                for (int nj = 0; nj < 4; nj++) mma_bf16(acc[mi][nj], afh[mi], bf[nj]);
            // pass 2: Alo * Bhi (afl short-lived)
            {
                uint32_t afl[4][4];
#pragma unroll
                for (int mi = 0; mi < 4; mi++) ldm_x4(afl[mi], aL + mi * (16 * RSTR) + kb);
#pragma unroll
                for (int mi = 0; mi < 4; mi++)
#pragma unroll
                    for (int nj = 0; nj < 4; nj++) mma_bf16(acc[mi][nj], afl[mi], bf[nj]);
            }
            // B-lo fragments (overwrite bf)
#pragma unroll
            for (int t = 0; t < 2; t++) {
                uint32_t tt[4];
                ldm_x4(tt, bL + t * (16 * RSTR) + kb);
                bf[2 * t][0] = tt[0]; bf[2 * t][1] = tt[1];
                bf[2 * t + 1][0] = tt[2]; bf[2 * t + 1][1] = tt[3];
            }
            // pass 3: Ahi * Blo
#pragma unroll
            for (int mi = 0; mi < 4; mi++)
#pragma unroll
                for (int nj = 0; nj < 4; nj++) mma_bf16(acc[mi][nj], afh[mi], bf[nj]);
        }
        __syncthreads();
    }

    // ---- epilogue ----
    const int act  = (int)((actlut >> (((bn * BN) >> 11) * 4)) & 15u);
    const int row0 = bm * BM + (lane >> 2);
    const int col0 = bn * BN + wn * 32 + 2 * (lane & 3);
#pragma unroll
    for (int mi = 0; mi < 4; mi++) {
#pragma unroll
        for (int nj = 0; nj < 4; nj++) {
            float2 v0, v1;
            v0.x = act_apply(acc[mi][nj][0], act);
            v0.y = act_apply(acc[mi][nj][1], act);
            v1.x = act_apply(acc[mi][nj][2], act);
            v1.y = act_apply(acc[mi][nj][3], act);
            size_t base = (size_t)(row0 + mi * 16) * ldc + col0 + nj * 8;
            *(float2*)(C + base)                   = v0;
            *(float2*)(C + base + (size_t)8 * ldc) = v1;
        }
    }
}

// ================= conversion kernels =================
__device__ __forceinline__ void split_bf16(float v, __nv_bfloat16& hi, __nv_bfloat16& lo) {
    hi = __float2bfloat16(v);
    lo = __float2bfloat16(v - __bfloat162float(hi));
}

__global__ void conv_x_kernel(const float* __restrict__ x,
                              __nv_bfloat16* __restrict__ hi, __nv_bfloat16* __restrict__ lo) {
    size_t i = (size_t)blockIdx.x * blockDim.x + threadIdx.x;
    split_bf16(x[i], hi[i], lo[i]);
}

__global__ void conv_w6_kernel(const float* __restrict__ w0, const float* __restrict__ w1,
                               const float* __restrict__ w2, const float* __restrict__ w3,
                               const float* __restrict__ w4, const float* __restrict__ w5,
                               __nv_bfloat16* __restrict__ hi, __nv_bfloat16* __restrict__ lo) {
    size_t i = (size_t)blockIdx.x * blockDim.x + threadIdx.x;     // [0, 12288*1024)
    int n = (int)(i >> 10);
    int k = (int)(i & 1023);
    int w = n >> 11, r = n & 2047;
    const float* src = (w == 0) ? w0 : (w == 1) ? w1 : (w == 2) ? w2
                     : (w == 3) ? w3 : (w == 4) ? w4 : w5;
    split_bf16(src[(size_t)r * 1024 + k], hi[i], lo[i]);
}

__global__ void conv_wout_kernel(const float* __restrict__ Wro, const float* __restrict__ Wd,
                                 __nv_bfloat16* __restrict__ hi, __nv_bfloat16* __restrict__ lo) {
    size_t i = (size_t)blockIdx.x * blockDim.x + threadIdx.x;     // [0, 1024*4096)
    int h = (int)(i >> 12);
    int j = (int)(i & 4095);
    float v = (j < 2048) ? Wro[(size_t)h * 2048 + j] : Wd[(size_t)h * 2048 + (j - 2048)];
    split_bf16(v, hi[i], lo[i]);
}

// ================= scan (two-level, chunked) =================
// P cols: f[0:2048) g[2048:4096) c[4096:6144) q[6144:8192) up[8192:10240) gate_silu[10240:12288)
__global__ void scanA_kernel(const float* __restrict__ P,
                             float* __restrict__ Fc, float* __restrict__ Gc) {
    int r  = blockIdx.x * blockDim.x + threadIdx.x;
    int bc = blockIdx.y;
    int b = bc >> 6, ch = bc & 63;
    const float* row = P + (size_t)(b * SDIM + ch * CH) * NPROJ;
    float F = 1.0f, G = 0.0f;
#pragma unroll 4
    for (int t = 0; t < CH; t++) {
        float f = row[r];
        float g = row[2048 + r];
        float c = row[4096 + r];
        G = fmaf(f, G, g * c);
        F *= f;
        row += NPROJ;
    }
    Fc[(size_t)bc * RDIM + r] = F;
    Gc[(size_t)bc * RDIM + r] = G;
}

__global__ void scanB_kernel(const float* __restrict__ Fc, const float* __restrict__ Gc,
                             const float* __restrict__ init, float* __restrict__ Sc) {
    int i = blockIdx.x * blockDim.x + threadIdx.x;
    int b = i >> 11, r = i & 2047;
    float state = init[r];
    for (int ch = 0; ch < NCH; ch++) {
        size_t idx = (size_t)(b * NCH + ch) * RDIM + r;
        Sc[idx] = state;
        state = fmaf(Fc[idx], state, Gc[idx]);
    }
}

__global__ void scanC_kernel(const float* __restrict__ P, const float* __restrict__ Sc,
                             __nv_bfloat16* __restrict__ a2hi, __nv_bfloat16* __restrict__ a2lo) {
    int r  = blockIdx.x * blockDim.x + threadIdx.x;
    int bc = blockIdx.y;
    int b = bc >> 6, ch = bc & 63;
    int m0 = b * SDIM + ch * CH;
    const float* row = P + (size_t)m0 * NPROJ;
    float state = Sc[(size_t)bc * RDIM + r];
#pragma unroll 4
    for (int t = 0; t < CH; t++) {
        float f = row[r];
        float g = row[2048 + r];
        float c = row[4096 + r];
        float q = row[6144 + r];
        state = fmaf(f, state, g * c);
        float z = q * state;
        float ro = z / (1.0f + __expf(-z));
        __nv_bfloat16 hi, lo;
        split_bf16(ro, hi, lo);
        size_t oi = (size_t)(m0 + t) * KOUT + r;
        a2hi[oi] = hi;
        a2lo[oi] = lo;
        row += NPROJ;
    }
}

__global__ void hcomb_kernel(const float* __restrict__ P,
                             __nv_bfloat16* __restrict__ a2hi, __nv_bfloat16* __restrict__ a2lo) {
    size_t i = (size_t)blockIdx.x * blockDim.x + threadIdx.x;
    int m = (int)(i >> 11);
    int l = (int)(i & 2047);
    const float* row = P + (size_t)m * NPROJ;
    float h = row[8192 + l] * row[10240 + l];
    __nv_bfloat16 hi, lo;
    split_bf16(h, hi, lo);
    size_t oi = (size_t)m * KOUT + 2048 + l;
    a2hi[oi] = hi;
    a2lo[oi] = lo;
}

// ================= launch =================
extern "C" void kernel_launch(void* const* d_in, const int* in_sizes, int n_in,
                              void* d_out, int out_size)
{
    const float* x    = (const float*)d_in[0];
    const float* Wf   = (const float*)d_in[1];
    const float* Wi   = (const float*)d_in[2];
    const float* Wv   = (const float*)d_in[3];
    const float* Wq   = (const float*)d_in[4];
    const float* Wro  = (const float*)d_in[5];
    const float* Wup  = (const float*)d_in[6];
    const float* Wg   = (const float*)d_in[7];
    const float* Wd   = (const float*)d_in[8];
    const float* init = (const float*)d_in[9];
    float* out = (float*)d_out;

    float *pP, *pFc, *pGc, *pSc;
    __nv_bfloat16 *pxhi, *pxlo, *pw6hi, *pw6lo, *pwohi, *pwolo, *pa2hi, *pa2lo;
    cudaGetSymbolAddress((void**)&pP,    g_P);
    cudaGetSymbolAddress((void**)&pxhi,  g_xhi);
    cudaGetSymbolAddress((void**)&pxlo,  g_xlo);
    cudaGetSymbolAddress((void**)&pw6hi, g_w6hi);
    cudaGetSymbolAddress((void**)&pw6lo, g_w6lo);
    cudaGetSymbolAddress((void**)&pwohi, g_wohi);
    cudaGetSymbolAddress((void**)&pwolo, g_wolo);
    cudaGetSymbolAddress((void**)&pa2hi, g_a2hi);
    cudaGetSymbolAddress((void**)&pa2lo, g_a2lo);
    cudaGetSymbolAddress((void**)&pFc,   g_Fc);
    cudaGetSymbolAddress((void**)&pGc,   g_Gc);
    cudaGetSymbolAddress((void**)&pSc,   g_Sc);

    cudaFuncSetAttribute(gemm_hmma, cudaFuncAttributeMaxDynamicSharedMemorySize, GEMM_SMEM);

    // conversions
    conv_x_kernel   <<<(MDIM * HDIM) / 256, 256>>>(x, pxhi, pxlo);
    conv_w6_kernel  <<<(NPROJ * HDIM) / 256, 256>>>(Wf, Wi, Wv, Wq, Wup, Wg, pw6hi, pw6lo);
    conv_wout_kernel<<<(HDIM * KOUT) / 256, 256>>>(Wro, Wd, pwohi, pwolo);

    // GEMM1: P = act( x @ W6^T ); acts per 2048-col block: tanh,sig,silu,none,none,silu
    {
        dim3 grid(NPROJ / BN, MDIM / BM);   // (96, 128)
        gemm_hmma<<<grid, 128, GEMM_SMEM>>>(pxhi, pxlo, pw6hi, pw6lo, HDIM, pP, NPROJ, 0x300321u);
    }

    // scan
    {
        dim3 gA(RDIM / 256, 4 * NCH);
        scanA_kernel<<<gA, 256>>>(pP, pFc, pGc);
        scanB_kernel<<<32, 256>>>(pFc, pGc, init, pSc);
        scanC_kernel<<<gA, 256>>>(pP, pSc, pa2hi, pa2lo);
        hcomb_kernel<<<(MDIM * RDIM) / 256, 256>>>(pP, pa2hi, pa2lo);
    }

    // GEMM2: out = [ro | h] @ [Wro | Wd]^T
    {
        dim3 grid(HDIM / BN, MDIM / BM);    // (8, 128)
        gemm_hmma<<<grid, 128, GEMM_SMEM>>>(pa2hi, pa2lo, pwohi, pwolo, KOUT, out, HDIM, 0u);
    }
}